// round 4
// baseline (speedup 1.0000x reference)
#include <cuda_runtime.h>

#define NQ 8192          // rows per side (users == items == 8192)
#define D 32             // q/k dim
#define DV 64            // V' dim (after folding W)
#define KNB 4            // neighbors
#define IN_DIM 256       // K*(D+D)

#define BM 64
#define BN 64
#define PAD 4
#define SK (BN + PAD)    // 68, row stride of transposed K tile
#define SQ (BM + PAD)    // 68
#define SV (DV + PAD)    // 68
#define SP (BM + PAD)    // 68

// Scratch: V' = cat @ W per side (2 x 2 MB)
__device__ float g_Vu[NQ * DV];
__device__ float g_Vi[NQ * DV];

// ---------------------------------------------------------------------------
// Phase 1: V'[u, :] = concat_k(vecA[idxA[u,k]], vecB[idxB[u,k]]) @ W
// Block: 128 threads, 8 users. Each thread: 1 user x 4 output cols (float4).
// ---------------------------------------------------------------------------
__global__ __launch_bounds__(128) void build_v_kernel(
    const float* __restrict__ vecA,   // review_vecs [*, 32]
    const int*   __restrict__ idxA,   // [NQ, 4]
    const float* __restrict__ vecB,   // item or user vecs [*, 32]
    const int*   __restrict__ idxB,   // [NQ, 4]
    const float* __restrict__ W,      // [256, 64]
    int side)                          // 0 -> g_Vu, 1 -> g_Vi
{
    __shared__ float cat_s[8][IN_DIM];
    const int tid = threadIdx.x;
    const int u0 = blockIdx.x * 8;

    // Gather 8 users x 256 features into smem
    for (int t = tid; t < 8 * IN_DIM; t += 128) {
        const int lu  = t >> 8;
        const int pos = t & 255;
        const int k   = pos >> 6;
        const int w   = pos & 63;
        const int gu  = u0 + lu;
        float v;
        if (w < 32) v = vecA[idxA[gu * KNB + k] * D + w];
        else        v = vecB[idxB[gu * KNB + k] * D + (w - 32)];
        cat_s[lu][pos] = v;
    }
    __syncthreads();

    const int lu = tid >> 4;    // 0..7
    const int og = tid & 15;    // 0..15 -> 4 output cols each
    const float4* W4 = reinterpret_cast<const float4*>(W);
    float4 acc = make_float4(0.f, 0.f, 0.f, 0.f);
#pragma unroll 8
    for (int i = 0; i < IN_DIM; i++) {
        const float c  = cat_s[lu][i];
        const float4 w4 = W4[i * 16 + og];
        acc.x += c * w4.x; acc.y += c * w4.y;
        acc.z += c * w4.z; acc.w += c * w4.w;
    }
    float* out = side ? g_Vi : g_Vu;
    reinterpret_cast<float4*>(out)[(u0 + lu) * 16 + og] = acc;
}

// ---------------------------------------------------------------------------
// Phase 2: fused flash attention (fp32), O = softmax(Q Q^T / sqrt(D) + 1) @ V'
// followed by ReLU.  Block: 256 threads = 16x16, each thread 4x4 S-subtile
// and 4x4 O-subtile.  BM=BN=64.  K tile and V tile share one smem buffer.
// ---------------------------------------------------------------------------
__global__ __launch_bounds__(256) void flash_kernel(
    const float* __restrict__ user_vecs,
    const float* __restrict__ item_vecs,
    float* __restrict__ out)
{
    __shared__ float Qt[D * SQ];           // transposed: Qt[dd][row]
    __shared__ float KVu[BN * SV];         // union: Kt[D][SK] / Vt[BN][SV]
    __shared__ float Pt[BN * SP];          // transposed P: Pt[col][row]

    const int side = blockIdx.y;
    const float* __restrict__ Q = side ? item_vecs : user_vecs;
    const float* __restrict__ V = side ? g_Vi : g_Vu;
    float* __restrict__ O = out + side * (NQ * DV);

    const int tid = threadIdx.x;
    const int ty = tid >> 4;    // 0..15 -> rows ty*4..+3
    const int tx = tid & 15;    // 0..15 -> cols tx*4..+3
    const int bm0 = blockIdx.x * BM;

    // Load Q tile transposed (once)
    for (int t = tid; t < BM * D; t += 256) {
        const int row = t >> 5, dd = t & 31;
        Qt[dd * SQ + row] = Q[(bm0 + row) * D + dd];
    }

    float m[4], l[4], acc[4][4];
#pragma unroll
    for (int r = 0; r < 4; r++) {
        m[r] = -1e30f; l[r] = 0.f;
#pragma unroll
        for (int c = 0; c < 4; c++) acc[r][c] = 0.f;
    }

    const float scale = 0.17677669529663687f;   // 1/sqrt(32)

    for (int j0 = 0; j0 < NQ; j0 += BN) {
        __syncthreads();   // previous Vt reads done (also orders Qt load, iter 0)
        // --- load K tile transposed into union buffer ---
        for (int t = tid; t < BN * D; t += 256) {
            const int row = t >> 5, dd = t & 31;
            KVu[dd * SK + row] = Q[(j0 + row) * D + dd];
        }
        __syncthreads();

        // --- S = Q K^T ---
        float s[4][4];
#pragma unroll
        for (int r = 0; r < 4; r++)
#pragma unroll
            for (int c = 0; c < 4; c++) s[r][c] = 0.f;

#pragma unroll 8
        for (int dd = 0; dd < D; dd++) {
            const float4 q4 = *reinterpret_cast<const float4*>(&Qt[dd * SQ + ty * 4]);
            const float4 k4 = *reinterpret_cast<const float4*>(&KVu[dd * SK + tx * 4]);
            s[0][0] += q4.x * k4.x; s[0][1] += q4.x * k4.y; s[0][2] += q4.x * k4.z; s[0][3] += q4.x * k4.w;
            s[1][0] += q4.y * k4.x; s[1][1] += q4.y * k4.y; s[1][2] += q4.y * k4.z; s[1][3] += q4.y * k4.w;
            s[2][0] += q4.z * k4.x; s[2][1] += q4.z * k4.y; s[2][2] += q4.z * k4.z; s[2][3] += q4.z * k4.w;
            s[3][0] += q4.w * k4.x; s[3][1] += q4.w * k4.y; s[3][2] += q4.w * k4.z; s[3][3] += q4.w * k4.w;
        }

        // --- online softmax update (row state replicated across 16 tx lanes) ---
        float p[4][4], corr[4];
#pragma unroll
        for (int r = 0; r < 4; r++) {
            float tmax = -1e30f;
#pragma unroll
            for (int c = 0; c < 4; c++) {
                s[r][c] = s[r][c] * scale + 1.0f;
                tmax = fmaxf(tmax, s[r][c]);
            }
#pragma unroll
            for (int o = 8; o >= 1; o >>= 1)
                tmax = fmaxf(tmax, __shfl_xor_sync(0xffffffffu, tmax, o));
            const float mn = fmaxf(m[r], tmax);
            corr[r] = __expf(m[r] - mn);
            float tsum = 0.f;
#pragma unroll
            for (int c = 0; c < 4; c++) {
                p[r][c] = __expf(s[r][c] - mn);
                tsum += p[r][c];
            }
#pragma unroll
            for (int o = 8; o >= 1; o >>= 1)
                tsum += __shfl_xor_sync(0xffffffffu, tsum, o);
            l[r] = l[r] * corr[r] + tsum;
            m[r] = mn;
        }

        // --- write P transposed: Pt[col][row] ---
#pragma unroll
        for (int cc = 0; cc < 4; cc++) {
            const float4 pv = make_float4(p[0][cc], p[1][cc], p[2][cc], p[3][cc]);
            *reinterpret_cast<float4*>(&Pt[(tx * 4 + cc) * SP + ty * 4]) = pv;
        }
        __syncthreads();   // Pt complete; Kt no longer needed

        // --- load V tile into union buffer (overwrites K tile) ---
        for (int t = tid * 4; t < BN * DV; t += 1024) {
            const int row = t >> 6, col = t & 63;
            *reinterpret_cast<float4*>(&KVu[row * SV + col]) =
                *reinterpret_cast<const float4*>(&V[(j0 + row) * DV + col]);
        }
        __syncthreads();

        // --- rescale O, accumulate P @ V ---
#pragma unroll
        for (int r = 0; r < 4; r++) {
            const float cr = corr[r];
#pragma unroll
            for (int c = 0; c < 4; c++) acc[r][c] *= cr;
        }
#pragma unroll 4
        for (int j = 0; j < BN; j++) {
            const float4 p4 = *reinterpret_cast<const float4*>(&Pt[j * SP + ty * 4]);
            const float4 v4 = *reinterpret_cast<const float4*>(&KVu[j * SV + tx * 4]);
            acc[0][0] += p4.x * v4.x; acc[0][1] += p4.x * v4.y; acc[0][2] += p4.x * v4.z; acc[0][3] += p4.x * v4.w;
            acc[1][0] += p4.y * v4.x; acc[1][1] += p4.y * v4.y; acc[1][2] += p4.y * v4.z; acc[1][3] += p4.y * v4.w;
            acc[2][0] += p4.z * v4.x; acc[2][1] += p4.z * v4.y; acc[2][2] += p4.z * v4.z; acc[2][3] += p4.z * v4.w;
            acc[3][0] += p4.w * v4.x; acc[3][1] += p4.w * v4.y; acc[3][2] += p4.w * v4.z; acc[3][3] += p4.w * v4.w;
        }
    }

    // --- epilogue: normalize, ReLU, store ---
#pragma unroll
    for (int r = 0; r < 4; r++) {
        const float inv = 1.f / l[r];
        const int row = bm0 + ty * 4 + r;
        const float4 o4 = make_float4(
            fmaxf(acc[r][0] * inv, 0.f),
            fmaxf(acc[r][1] * inv, 0.f),
            fmaxf(acc[r][2] * inv, 0.f),
            fmaxf(acc[r][3] * inv, 0.f));
        *reinterpret_cast<float4*>(&O[row * DV + tx * 4]) = o4;
    }
}

// ---------------------------------------------------------------------------
// Launch
// ---------------------------------------------------------------------------
extern "C" void kernel_launch(void* const* d_in, const int* in_sizes, int n_in,
                              void* d_out, int out_size)
{
    (void)in_sizes; (void)n_in; (void)out_size;
    const float* review = (const float*)d_in[0];
    const float* user   = (const float*)d_in[1];
    const float* item   = (const float*)d_in[2];
    const int*   adj_ur = (const int*)d_in[3];
    const int*   adj_ri = (const int*)d_in[4];
    const int*   adj_ir = (const int*)d_in[5];
    const int*   adj_ru = (const int*)d_in[6];
    const float* Wu     = (const float*)d_in[7];
    const float* Wi     = (const float*)d_in[8];
    float* out = (float*)d_out;

    // Phase 1: fold gather+concat+W into V' per side
    build_v_kernel<<<NQ / 8, 128>>>(review, adj_ur, item, adj_ri, Wu, 0);
    build_v_kernel<<<NQ / 8, 128>>>(review, adj_ir, user, adj_ru, Wi, 1);

    // Phase 2: fused attention for both sides
    dim3 grid(NQ / BM, 2);
    flash_kernel<<<grid, 256>>>(user, item, out);
}

// round 6
// speedup vs baseline: 3.4762x; 3.4762x over previous
#include <cuda_runtime.h>
#include <cuda_bf16.h>
#include <cstdint>

#define NQ 8192
#define D 32
#define DV 64
#define KNB 4
#define IN_DIM 256

#define BM 128
#define BN 64
#define NITER (NQ / BN)   // 128
#define STRIDE 72         // bf16 elems per smem row (64 data + 8 pad) = 144 B
#define SBYTES 144

// ---------------- device scratch ----------------
__device__ float g_Vu[NQ * DV];
__device__ float g_Vi[NQ * DV];
__device__ __nv_bfloat16 g_Qs[2 * NQ * 64];      // [side][row][hi32|lo32]
__device__ __nv_bfloat16 g_Vt[2 * 2 * DV * NQ];  // [side][hi/lo][n][j]

// ---------------- helpers (plain PTX, sm_80+ features only) ----------------
__device__ __forceinline__ uint32_t smem_u32(const void* p) {
    uint32_t a;
    asm("{ .reg .u64 t; cvta.to.shared.u64 t, %1; cvt.u32.u64 %0, t; }" : "=r"(a) : "l"(p));
    return a;
}
__device__ __forceinline__ void ldsm4(uint32_t r[4], uint32_t addr) {
    asm volatile("ldmatrix.sync.aligned.m8n8.x4.shared.b16 {%0,%1,%2,%3}, [%4];"
                 : "=r"(r[0]), "=r"(r[1]), "=r"(r[2]), "=r"(r[3]) : "r"(addr));
}
__device__ __forceinline__ void mma_bf16(float d[4], const uint32_t a[4], const uint32_t b[2]) {
    asm volatile(
        "mma.sync.aligned.m16n8k16.row.col.f32.bf16.bf16.f32 "
        "{%0,%1,%2,%3}, {%4,%5,%6,%7}, {%8,%9}, {%0,%1,%2,%3};"
        : "+f"(d[0]), "+f"(d[1]), "+f"(d[2]), "+f"(d[3])
        : "r"(a[0]), "r"(a[1]), "r"(a[2]), "r"(a[3]), "r"(b[0]), "r"(b[1]));
}
__device__ __forceinline__ float ex2f(float x) {
    float y; asm("ex2.approx.ftz.f32 %0, %1;" : "=f"(y) : "f"(x)); return y;
}
__device__ __forceinline__ uint32_t packbf2(float a, float b) {
    __nv_bfloat162 h(__float2bfloat16(a), __float2bfloat16(b));  // a -> low half
    return *reinterpret_cast<uint32_t*>(&h);
}
#define CP16(dst, src) \
    asm volatile("cp.async.cg.shared.global [%0], [%1], 16;" :: "r"(dst), "l"(src))
#define CP_COMMIT() asm volatile("cp.async.commit_group;" ::: "memory")
#define CP_WAIT1()  asm volatile("cp.async.wait_group 1;" ::: "memory")
#define CP_WAIT0()  asm volatile("cp.async.wait_group 0;" ::: "memory")

// smem offsets (bytes)
#define OFF_Q  0                         // 128 x 144 = 18432
#define OFF_K  18432                     // 2 bufs x 64 x 144 = 18432
#define OFF_VH 36864                     // 2 bufs
#define OFF_VL 55296                     // 2 bufs
#define SMEM_TOTAL 73728
#define BUF 9216

// ---------------------------------------------------------------------------
// Phase 1a: V'[u,:] = concat_k(vecA[idxA], vecB[idxB]) @ W
// ---------------------------------------------------------------------------
__global__ __launch_bounds__(128) void build_v_kernel(
    const float* __restrict__ vecA, const int* __restrict__ idxA,
    const float* __restrict__ vecB, const int* __restrict__ idxB,
    const float* __restrict__ W, int side)
{
    __shared__ float cat_s[8][IN_DIM];
    const int tid = threadIdx.x;
    const int u0 = blockIdx.x * 8;
    for (int t = tid; t < 8 * IN_DIM; t += 128) {
        const int lu = t >> 8, pos = t & 255, k = pos >> 6, w = pos & 63;
        const int gu = u0 + lu;
        float v;
        if (w < 32) v = vecA[idxA[gu * KNB + k] * D + w];
        else        v = vecB[idxB[gu * KNB + k] * D + (w - 32)];
        cat_s[lu][pos] = v;
    }
    __syncthreads();
    const int lu = tid >> 4, og = tid & 15;
    const float4* W4 = reinterpret_cast<const float4*>(W);
    float4 acc = make_float4(0.f, 0.f, 0.f, 0.f);
#pragma unroll 8
    for (int i = 0; i < IN_DIM; i++) {
        const float c = cat_s[lu][i];
        const float4 w4 = W4[i * 16 + og];
        acc.x += c * w4.x; acc.y += c * w4.y; acc.z += c * w4.z; acc.w += c * w4.w;
    }
    float* out = side ? g_Vi : g_Vu;
    reinterpret_cast<float4*>(out)[(u0 + lu) * 16 + og] = acc;
}

// ---------------------------------------------------------------------------
// Phase 1b: Q -> bf16 hi/lo, row layout [hi(0..31) | lo(0..31)]
// ---------------------------------------------------------------------------
__global__ __launch_bounds__(256) void split_q_kernel(
    const float* __restrict__ user_vecs, const float* __restrict__ item_vecs)
{
    int idx = blockIdx.x * 256 + threadIdx.x;
    if (idx >= 2 * NQ * D) return;
    int side = idx / (NQ * D);
    int r = idx % (NQ * D);
    int row = r >> 5, col = r & 31;
    const float* Q = side ? item_vecs : user_vecs;
    float x = Q[row * D + col];
    __nv_bfloat16 h = __float2bfloat16(x);
    float lo = x - __bfloat162float(h);
    __nv_bfloat16* dst = g_Qs + ((size_t)side * NQ + row) * 64;
    dst[col]      = h;
    dst[32 + col] = __float2bfloat16(lo);
}

// ---------------------------------------------------------------------------
// Phase 1c: split + transpose V' -> g_Vt[side][h][n][j]
// ---------------------------------------------------------------------------
__global__ __launch_bounds__(256) void split_v_kernel()
{
    __shared__ float s[64][65];
    const int side = blockIdx.y;
    const int j0 = blockIdx.x * 64;
    const float* V = side ? g_Vi : g_Vu;
    for (int t = threadIdx.x; t < 64 * 64; t += 256) {
        int j = t >> 6, n = t & 63;
        s[j][n] = V[(j0 + j) * DV + n];
    }
    __syncthreads();
    for (int t = threadIdx.x; t < 64 * 64; t += 256) {
        int n = t >> 6, j = t & 63;
        float x = s[j][n];
        __nv_bfloat16 h = __float2bfloat16(x);
        float r = x - __bfloat162float(h);
        g_Vt[(((size_t)side * 2 + 0) * DV + n) * NQ + j0 + j] = h;
        g_Vt[(((size_t)side * 2 + 1) * DV + n) * NQ + j0 + j] = __float2bfloat16(r);
    }
}

// ---------------------------------------------------------------------------
// Phase 2: HMMA flash attention.  256 thr = 8 warps x 16 rows.
// S/O live in register fragments; P repacked regs->regs into A fragments.
// K/V tiles double-buffered in smem via cp.async.
// ---------------------------------------------------------------------------
__global__ __launch_bounds__(256, 1) void flash_mma_kernel(float* __restrict__ out)
{
    extern __shared__ char smem[];
    const uint32_t sb = smem_u32(smem);
    const int tid = threadIdx.x;
    const int w = tid >> 5, lane = tid & 31;
    const int side = blockIdx.y;
    const int bm0 = blockIdx.x * BM;

    const __nv_bfloat16* Qside = g_Qs + (size_t)side * NQ * 64;
    const __nv_bfloat16* VtH = g_Vt + ((size_t)side * 2 + 0) * DV * NQ;
    const __nv_bfloat16* VtL = g_Vt + ((size_t)side * 2 + 1) * DV * NQ;

    // ---- cp.async issue helpers ----
    // Q tile: 128 rows x 8 chunks(16B) = 1024 chunks -> 4/thread
    {
#pragma unroll
        for (int i = 0; i < 4; i++) {
            int t = tid + 256 * i;
            int r = t >> 3, seg = t & 7;
            CP16(sb + OFF_Q + r * SBYTES + seg * 16,
                 Qside + (size_t)(bm0 + r) * 64 + seg * 8);
        }
    }
    // tile 0 (K + VH + VL): 1536 chunks -> 6/thread
    {
        const int j0 = 0;
#pragma unroll
        for (int i = 0; i < 6; i++) {
            int t = tid + 256 * i;
            int arr = t >> 9, rem = t & 511;
            int r = rem >> 3, seg = rem & 7;
            const __nv_bfloat16* src;
            uint32_t dst;
            if (arr == 0)      { src = Qside + (size_t)(j0 + r) * 64 + seg * 8;   dst = sb + OFF_K  + r * SBYTES + seg * 16; }
            else if (arr == 1) { src = VtH + (size_t)r * NQ + j0 + seg * 8;       dst = sb + OFF_VH + r * SBYTES + seg * 16; }
            else               { src = VtL + (size_t)r * NQ + j0 + seg * 8;       dst = sb + OFF_VL + r * SBYTES + seg * 16; }
            CP16(dst, src);
        }
    }
    CP_COMMIT();

    uint32_t qh[2][4], ql[2][4];
    float o[8][4];
#pragma unroll
    for (int nt = 0; nt < 8; nt++)
#pragma unroll
        for (int i = 0; i < 4; i++) o[nt][i] = 0.f;
    float lsum0 = 0.f, lsum1 = 0.f;
    const float C = 0.25503486f;   // log2(e)/sqrt(32)

    // ldmatrix address pieces (per-lane)
    const int aRow = (lane & 7) + ((lane >> 3) & 1) * 8;   // A pattern row
    const int aCol = ((lane >> 4) & 1) * 16;               // A pattern col bytes
    const int bRow = lane & 7;                             // B pattern row
    const int bCol = (lane >> 3) * 16;                     // B pattern col bytes

    for (int it = 0; it < NITER; ++it) {
        const int cur = it & 1;
        if (it + 1 < NITER) {
            const int j0 = (it + 1) * BN;
            const int nb = (it + 1) & 1;
#pragma unroll
            for (int i = 0; i < 6; i++) {
                int t = tid + 256 * i;
                int arr = t >> 9, rem = t & 511;
                int r = rem >> 3, seg = rem & 7;
                const __nv_bfloat16* src;
                uint32_t dst;
                if (arr == 0)      { src = Qside + (size_t)(j0 + r) * 64 + seg * 8;   dst = sb + OFF_K  + nb * BUF + r * SBYTES + seg * 16; }
                else if (arr == 1) { src = VtH + (size_t)r * NQ + j0 + seg * 8;       dst = sb + OFF_VH + nb * BUF + r * SBYTES + seg * 16; }
                else               { src = VtL + (size_t)r * NQ + j0 + seg * 8;       dst = sb + OFF_VL + nb * BUF + r * SBYTES + seg * 16; }
                CP16(dst, src);
            }
            CP_COMMIT();
            CP_WAIT1();
        } else {
            CP_WAIT0();
        }
        __syncthreads();

        if (it == 0) {
            // Q fragments (persistent): rows 16w..16w+15, cols hi 0-31, lo 32-63
            const uint32_t qbase = sb + OFF_Q + (16 * w) * SBYTES + aRow * SBYTES + aCol;
            ldsm4(qh[0], qbase + 0);
            ldsm4(qh[1], qbase + 32);
            ldsm4(ql[0], qbase + 64);
            ldsm4(ql[1], qbase + 96);
        }

        // ---- S = Q K^T (split-bf16, 3 products) ----
        float s[8][4];
#pragma unroll
        for (int nt = 0; nt < 8; nt++)
#pragma unroll
            for (int i = 0; i < 4; i++) s[nt][i] = 0.f;

        const uint32_t kbase = sb + OFF_K + cur * BUF + bRow * SBYTES + bCol;
#pragma unroll
        for (int nt = 0; nt < 8; nt++) {
            uint32_t kh[4], kl[4];
            ldsm4(kh, kbase + (8 * nt) * SBYTES + 0);
            ldsm4(kl, kbase + (8 * nt) * SBYTES + 64);
            mma_bf16(s[nt], qh[0], kh + 0);
            mma_bf16(s[nt], qh[1], kh + 2);
            mma_bf16(s[nt], qh[0], kl + 0);
            mma_bf16(s[nt], qh[1], kl + 2);
            mma_bf16(s[nt], ql[0], kh + 0);
            mma_bf16(s[nt], ql[1], kh + 2);
        }

        // ---- exp (unnormalized), row-sum, repack to A fragments ----
        float p[8][4];
#pragma unroll
        for (int nt = 0; nt < 8; nt++) {
#pragma unroll
            for (int i = 0; i < 4; i++) p[nt][i] = ex2f(s[nt][i] * C);
            lsum0 += p[nt][0] + p[nt][1];
            lsum1 += p[nt][2] + p[nt][3];
        }
        uint32_t phi[4][4], plo[4][4];
#pragma unroll
        for (int c = 0; c < 4; c++) {
#pragma unroll
            for (int h = 0; h < 4; h++) {
                const int nt = 2 * c + (h >> 1);
                const float a = p[nt][(h & 1) * 2 + 0];
                const float b = p[nt][(h & 1) * 2 + 1];
                const float ah = __bfloat162float(__float2bfloat16(a));
                const float bh = __bfloat162float(__float2bfloat16(b));
                phi[c][h] = packbf2(ah, bh);
                plo[c][h] = packbf2(a - ah, b - bh);
            }
        }

        // ---- O += P @ V' (split products: PhVh + PhVl + PlVh) ----
        const uint32_t vhb = sb + OFF_VH + cur * BUF + bRow * SBYTES + bCol;
        const uint32_t vlb = sb + OFF_VL + cur * BUF + bRow * SBYTES + bCol;
#pragma unroll
        for (int nt = 0; nt < 8; nt++) {
            uint32_t vh[8], vl[8];
            ldsm4(vh + 0, vhb + (8 * nt) * SBYTES + 0);
            ldsm4(vh + 4, vhb + (8 * nt) * SBYTES + 64);
            ldsm4(vl + 0, vlb + (8 * nt) * SBYTES + 0);
            ldsm4(vl + 4, vlb + (8 * nt) * SBYTES + 64);
#pragma unroll
            for (int c = 0; c < 4; c++) {
                mma_bf16(o[nt], phi[c], vh + 2 * c);
                mma_bf16(o[nt], phi[c], vl + 2 * c);
                mma_bf16(o[nt], plo[c], vh + 2 * c);
            }
        }
        __syncthreads();
    }

    // ---- epilogue: reduce row sums across quad, normalize, ReLU, store ----
    lsum0 += __shfl_xor_sync(0xffffffffu, lsum0, 1);
    lsum0 += __shfl_xor_sync(0xffffffffu, lsum0, 2);
    lsum1 += __shfl_xor_sync(0xffffffffu, lsum1, 1);
    lsum1 += __shfl_xor_sync(0xffffffffu, lsum1, 2);
    const float inv0 = 1.f / lsum0;
    const float inv1 = 1.f / lsum1;

    const int row0 = bm0 + 16 * w + (lane >> 2);
    float* obase = out + (size_t)side * NQ * DV;
    const int coff = 2 * (lane & 3);
#pragma unroll
    for (int nt = 0; nt < 8; nt++) {
        float2 v0 = make_float2(fmaxf(o[nt][0] * inv0, 0.f), fmaxf(o[nt][1] * inv0, 0.f));
        float2 v1 = make_float2(fmaxf(o[nt][2] * inv1, 0.f), fmaxf(o[nt][3] * inv1, 0.f));
        *reinterpret_cast<float2*>(obase + (size_t)row0 * DV + 8 * nt + coff) = v0;
        *reinterpret_cast<float2*>(obase + (size_t)(row0 + 8) * DV + 8 * nt + coff) = v1;
    }
}

// ---------------------------------------------------------------------------
extern "C" void kernel_launch(void* const* d_in, const int* in_sizes, int n_in,
                              void* d_out, int out_size)
{
    (void)in_sizes; (void)n_in; (void)out_size;
    const float* review = (const float*)d_in[0];
    const float* user   = (const float*)d_in[1];
    const float* item   = (const float*)d_in[2];
    const int*   adj_ur = (const int*)d_in[3];
    const int*   adj_ri = (const int*)d_in[4];
    const int*   adj_ir = (const int*)d_in[5];
    const int*   adj_ru = (const int*)d_in[6];
    const float* Wu     = (const float*)d_in[7];
    const float* Wi     = (const float*)d_in[8];
    float* out = (float*)d_out;

    cudaFuncSetAttribute(flash_mma_kernel,
                         cudaFuncAttributeMaxDynamicSharedMemorySize, SMEM_TOTAL);

    build_v_kernel<<<NQ / 8, 128>>>(review, adj_ur, item, adj_ri, Wu, 0);
    build_v_kernel<<<NQ / 8, 128>>>(review, adj_ir, user, adj_ru, Wi, 1);
    split_q_kernel<<<(2 * NQ * D + 255) / 256, 256>>>(user, item);
    split_v_kernel<<<dim3(NQ / 64, 2), 256>>>();

    dim3 grid(NQ / BM, 2);
    flash_mma_kernel<<<grid, 256, SMEM_TOTAL>>>(out);
}

// round 8
// speedup vs baseline: 3.5923x; 1.0334x over previous
#include <cuda_runtime.h>
#include <cuda_bf16.h>
#include <cuda_fp16.h>
#include <cstdint>

#define NQ 8192
#define D 32
#define DV 64
#define KNB 4
#define IN_DIM 256

#define BM 128
#define BN 64
#define NITER (NQ / BN)   // 128
#define SBYTES 144        // 128B data + 16B pad per smem row

// ---------------- device scratch ----------------
__device__ float g_Vu[NQ * DV];
__device__ float g_Vi[NQ * DV];
__device__ __nv_bfloat16 g_Qs[2 * NQ * 64];   // [side][row][hi32|lo32] bf16
__device__ __half g_Vth[2 * DV * NQ];         // [side][n][j] fp16 hi
__device__ __half g_Vtl[2 * DV * NQ];         // [side][n][j] fp16 lo (residual)

// ---------------- PTX helpers ----------------
__device__ __forceinline__ uint32_t smem_u32(const void* p) {
    uint32_t a;
    asm("{ .reg .u64 t; cvta.to.shared.u64 t, %1; cvt.u32.u64 %0, t; }" : "=r"(a) : "l"(p));
    return a;
}
__device__ __forceinline__ void ldsm4(uint32_t r[4], uint32_t addr) {
    asm volatile("ldmatrix.sync.aligned.m8n8.x4.shared.b16 {%0,%1,%2,%3}, [%4];"
                 : "=r"(r[0]), "=r"(r[1]), "=r"(r[2]), "=r"(r[3]) : "r"(addr));
}
__device__ __forceinline__ void mma_bf16(float d[4], const uint32_t a[4], const uint32_t b[2]) {
    asm volatile(
        "mma.sync.aligned.m16n8k16.row.col.f32.bf16.bf16.f32 "
        "{%0,%1,%2,%3}, {%4,%5,%6,%7}, {%8,%9}, {%0,%1,%2,%3};"
        : "+f"(d[0]), "+f"(d[1]), "+f"(d[2]), "+f"(d[3])
        : "r"(a[0]), "r"(a[1]), "r"(a[2]), "r"(a[3]), "r"(b[0]), "r"(b[1]));
}
__device__ __forceinline__ void mma_fp16(float d[4], const uint32_t a[4], const uint32_t b[2]) {
    asm volatile(
        "mma.sync.aligned.m16n8k16.row.col.f32.f16.f16.f32 "
        "{%0,%1,%2,%3}, {%4,%5,%6,%7}, {%8,%9}, {%0,%1,%2,%3};"
        : "+f"(d[0]), "+f"(d[1]), "+f"(d[2]), "+f"(d[3])
        : "r"(a[0]), "r"(a[1]), "r"(a[2]), "r"(a[3]), "r"(b[0]), "r"(b[1]));
}
__device__ __forceinline__ float ex2f(float x) {
    float y; asm("ex2.approx.ftz.f32 %0, %1;" : "=f"(y) : "f"(x)); return y;
}
__device__ __forceinline__ uint32_t packh2(float a, float b) {
    __half2 h = __floats2half2_rn(a, b);          // a -> low half
    return *reinterpret_cast<uint32_t*>(&h);
}
#define CP16(dst, src) \
    asm volatile("cp.async.cg.shared.global [%0], [%1], 16;" :: "r"(dst), "l"(src))
#define CP_COMMIT() asm volatile("cp.async.commit_group;" ::: "memory")
#define CP_WAIT1()  asm volatile("cp.async.wait_group 1;" ::: "memory")
#define CP_WAIT0()  asm volatile("cp.async.wait_group 0;" ::: "memory")

// flash smem layout (bytes)
#define OFF_Q  0                    // 128 x 144
#define OFF_K  18432                // 2 bufs x 64 x 144
#define OFF_VH 36864                // 2 bufs
#define OFF_VL 55296                // 2 bufs
#define SMEM_FLASH 73728
#define BUF 9216

// ---------------------------------------------------------------------------
// Phase 1a: V'[u,:] = concat_k(vecA[idxA], vecB[idxB]) @ W
// One launch, grid.y = side, W staged in smem, 32 users/block.
// ---------------------------------------------------------------------------
__global__ __launch_bounds__(256) void build_v_kernel(
    const float* __restrict__ review,
    const float* __restrict__ user, const float* __restrict__ item,
    const int* __restrict__ adj_ur, const int* __restrict__ adj_ri,
    const int* __restrict__ adj_ir, const int* __restrict__ adj_ru,
    const float* __restrict__ Wu, const float* __restrict__ Wi)
{
    extern __shared__ float sm[];                 // W[16384] | cat[32][256]
    float* Wsm = sm;
    float* cat = sm + IN_DIM * DV;

    const int side = blockIdx.y;
    const float* vecA = review;
    const int*   idxA = side ? adj_ir : adj_ur;
    const float* vecB = side ? user : item;
    const int*   idxB = side ? adj_ru : adj_ri;
    const float* W    = side ? Wi : Wu;

    const int tid = threadIdx.x;
    const int u0 = blockIdx.x * 32;

    for (int t = tid; t < IN_DIM * DV / 4; t += 256)
        reinterpret_cast<float4*>(Wsm)[t] = reinterpret_cast<const float4*>(W)[t];

    for (int t = tid; t < 32 * IN_DIM; t += 256) {
        const int lu = t >> 8, pos = t & 255, k = pos >> 6, w = pos & 63;
        const int gu = u0 + lu;
        float v;
        if (w < 32) v = vecA[idxA[gu * KNB + k] * D + w];
        else        v = vecB[idxB[gu * KNB + k] * D + (w - 32)];
        cat[lu * IN_DIM + pos] = v;
    }
    __syncthreads();

    const int lu = tid >> 3;
    const int og = tid & 7;
    const float4* W4 = reinterpret_cast<const float4*>(Wsm);
    float4 a0 = make_float4(0.f, 0.f, 0.f, 0.f);
    float4 a1 = make_float4(0.f, 0.f, 0.f, 0.f);
#pragma unroll 8
    for (int i = 0; i < IN_DIM; i++) {
        const float c = cat[lu * IN_DIM + i];
        const float4 w0 = W4[i * 16 + og * 2];
        const float4 w1 = W4[i * 16 + og * 2 + 1];
        a0.x += c * w0.x; a0.y += c * w0.y; a0.z += c * w0.z; a0.w += c * w0.w;
        a1.x += c * w1.x; a1.y += c * w1.y; a1.z += c * w1.z; a1.w += c * w1.w;
    }
    float* out = side ? g_Vi : g_Vu;
    reinterpret_cast<float4*>(out)[(u0 + lu) * 16 + og * 2]     = a0;
    reinterpret_cast<float4*>(out)[(u0 + lu) * 16 + og * 2 + 1] = a1;
}
#define SMEM_BUILD ((IN_DIM * DV + 32 * IN_DIM) * 4)   // 96 KB

// ---------------------------------------------------------------------------
// Phase 1b: Q -> bf16 hi/lo, row layout [hi(0..31) | lo(0..31)]
// ---------------------------------------------------------------------------
__global__ __launch_bounds__(256) void split_q_kernel(
    const float* __restrict__ user_vecs, const float* __restrict__ item_vecs)
{
    int idx = blockIdx.x * 256 + threadIdx.x;
    if (idx >= 2 * NQ * D) return;
    int side = idx / (NQ * D);
    int r = idx % (NQ * D);
    int row = r >> 5, col = r & 31;
    const float* Q = side ? item_vecs : user_vecs;
    float x = Q[row * D + col];
    __nv_bfloat16 h = __float2bfloat16(x);
    float lo = x - __bfloat162float(h);
    __nv_bfloat16* dst = g_Qs + ((size_t)side * NQ + row) * 64;
    dst[col]      = h;
    dst[32 + col] = __float2bfloat16(lo);
}

// ---------------------------------------------------------------------------
// Phase 1c: transpose + split V' -> fp16 hi/lo planes [side][n][j]
// ---------------------------------------------------------------------------
__global__ __launch_bounds__(256) void split_v_kernel()
{
    __shared__ float s[64][65];
    const int side = blockIdx.y;
    const int j0 = blockIdx.x * 64;
    const float* V = side ? g_Vi : g_Vu;
    for (int t = threadIdx.x; t < 64 * 64; t += 256) {
        int j = t >> 6, n = t & 63;
        s[j][n] = V[(j0 + j) * DV + n];
    }
    __syncthreads();
    for (int t = threadIdx.x; t < 64 * 64; t += 256) {
        int n = t >> 6, j = t & 63;
        float x = s[j][n];
        __half h = __float2half_rn(x);
        float r = x - __half2float(h);
        g_Vth[((size_t)side * DV + n) * NQ + j0 + j] = h;
        g_Vtl[((size_t)side * DV + n) * NQ + j0 + j] = __float2half_rn(r);
    }
}

// ---------------------------------------------------------------------------
// Phase 2: HMMA flash attention.  8 warps, BM=128, BN=64.
// QK: split-bf16, 3 products (proven 4e-5).
// PV: P fp16 (exp biased by e^-8), V fp16 hi+lo, 2 products.
// ---------------------------------------------------------------------------
__global__ __launch_bounds__(256, 1) void flash_mma_kernel(float* __restrict__ out)
{
    extern __shared__ char smem[];
    const uint32_t sb = smem_u32(smem);
    const int tid = threadIdx.x;
    const int w = tid >> 5, lane = tid & 31;
    const int side = blockIdx.y;
    const int bm0 = blockIdx.x * BM;

    const __nv_bfloat16* Qside = g_Qs + (size_t)side * NQ * 64;
    const __half* VtH = g_Vth + (size_t)side * DV * NQ;
    const __half* VtL = g_Vtl + (size_t)side * DV * NQ;

    // Q tile: 1024 16B chunks -> 4/thread
#pragma unroll
    for (int i = 0; i < 4; i++) {
        int t = tid + 256 * i;
        int r = t >> 3, seg = t & 7;
        CP16(sb + OFF_Q + r * SBYTES + seg * 16,
             Qside + (size_t)(bm0 + r) * 64 + seg * 8);
    }
    // tile 0 (K + VH + VL): 1536 chunks -> 6/thread
#pragma unroll
    for (int i = 0; i < 6; i++) {
        int t = tid + 256 * i;
        int arr = t >> 9, rem = t & 511;
        int r = rem >> 3, seg = rem & 7;
        if (arr == 0)
            CP16(sb + OFF_K + r * SBYTES + seg * 16, Qside + (size_t)r * 64 + seg * 8);
        else if (arr == 1)
            CP16(sb + OFF_VH + r * SBYTES + seg * 16, VtH + (size_t)r * NQ + seg * 8);
        else
            CP16(sb + OFF_VL + r * SBYTES + seg * 16, VtL + (size_t)r * NQ + seg * 8);
    }
    CP_COMMIT();

    uint32_t qh[2][4], ql[2][4];
    float o[8][4];
#pragma unroll
    for (int nt = 0; nt < 8; nt++)
#pragma unroll
        for (int i = 0; i < 4; i++) o[nt][i] = 0.f;
    float lsum0 = 0.f, lsum1 = 0.f;
    const float C  = 0.25503486f;    // log2(e)/sqrt(32)
    const float B2 = 11.5415603f;    // 8*log2(e)  (p' = 2^(sC - B2) = e^(s/sqrt32 - 8))

    const int aRow = (lane & 7) + ((lane >> 3) & 1) * 8;
    const int aCol = ((lane >> 4) & 1) * 16;
    const int bRow = lane & 7;
    const int bCol = (lane >> 3) * 16;

    for (int it = 0; it < NITER; ++it) {
        const int cur = it & 1;
        if (it + 1 < NITER) {
            const int j0 = (it + 1) * BN;
            const int nb = (it + 1) & 1;
#pragma unroll
            for (int i = 0; i < 6; i++) {
                int t = tid + 256 * i;
                int arr = t >> 9, rem = t & 511;
                int r = rem >> 3, seg = rem & 7;
                if (arr == 0)
                    CP16(sb + OFF_K + nb * BUF + r * SBYTES + seg * 16,
                         Qside + (size_t)(j0 + r) * 64 + seg * 8);
                else if (arr == 1)
                    CP16(sb + OFF_VH + nb * BUF + r * SBYTES + seg * 16,
                         VtH + (size_t)r * NQ + j0 + seg * 8);
                else
                    CP16(sb + OFF_VL + nb * BUF + r * SBYTES + seg * 16,
                         VtL + (size_t)r * NQ + j0 + seg * 8);
            }
            CP_COMMIT();
            CP_WAIT1();
        } else {
            CP_WAIT0();
        }
        __syncthreads();

        if (it == 0) {
            const uint32_t qbase = sb + OFF_Q + (16 * w) * SBYTES + aRow * SBYTES + aCol;
            ldsm4(qh[0], qbase + 0);
            ldsm4(qh[1], qbase + 32);
            ldsm4(ql[0], qbase + 64);
            ldsm4(ql[1], qbase + 96);
        }

        // ---- S = Q K^T (split-bf16, 3 products) ----
        float s[8][4];
#pragma unroll
        for (int nt = 0; nt < 8; nt++)
#pragma unroll
            for (int i = 0; i < 4; i++) s[nt][i] = 0.f;

        const uint32_t kbase = sb + OFF_K + cur * BUF + bRow * SBYTES + bCol;
#pragma unroll
        for (int nt = 0; nt < 8; nt++) {
            uint32_t kh[4], kl[4];
            ldsm4(kh, kbase + (8 * nt) * SBYTES + 0);
            ldsm4(kl, kbase + (8 * nt) * SBYTES + 64);
            mma_bf16(s[nt], qh[0], kh + 0);
            mma_bf16(s[nt], qh[1], kh + 2);
            mma_bf16(s[nt], qh[0], kl + 0);
            mma_bf16(s[nt], qh[1], kl + 2);
            mma_bf16(s[nt], ql[0], kh + 0);
            mma_bf16(s[nt], ql[1], kh + 2);
        }

        // ---- exp (biased, unnormalized), row-sum, pack to fp16 A fragments ----
        float p[8][4];
#pragma unroll
        for (int nt = 0; nt < 8; nt++) {
#pragma unroll
            for (int i = 0; i < 4; i++) p[nt][i] = ex2f(s[nt][i] * C - B2);
            lsum0 += p[nt][0] + p[nt][1];
            lsum1 += p[nt][2] + p[nt][3];
        }
        uint32_t phi[4][4];
#pragma unroll
        for (int c = 0; c < 4; c++) {
#pragma unroll
            for (int h = 0; h < 4; h++) {
                const int nt = 2 * c + (h >> 1);
                phi[c][h] = packh2(p[nt][(h & 1) * 2 + 0], p[nt][(h & 1) * 2 + 1]);
            }
        }

        // ---- O += Ph @ (Vh + Vl)  (fp16, 2 products) ----
        const uint32_t vhb = sb + OFF_VH + cur * BUF + bRow * SBYTES + bCol;
        const uint32_t vlb = sb + OFF_VL + cur * BUF + bRow * SBYTES + bCol;
#pragma unroll
        for (int nt = 0; nt < 8; nt++) {
            uint32_t vh[8], vl[8];
            ldsm4(vh + 0, vhb + (8 * nt) * SBYTES + 0);
            ldsm4(vh + 4, vhb + (8 * nt) * SBYTES + 64);
            ldsm4(vl + 0, vlb + (8 * nt) * SBYTES + 0);
            ldsm4(vl + 4, vlb + (8 * nt) * SBYTES + 64);
#pragma unroll
            for (int c = 0; c < 4; c++) {
                mma_fp16(o[nt], phi[c], vh + 2 * c);
                mma_fp16(o[nt], phi[c], vl + 2 * c);
            }
        }
        __syncthreads();
    }

    // ---- epilogue: quad-reduce row sums, normalize, ReLU, store ----
    lsum0 += __shfl_xor_sync(0xffffffffu, lsum0, 1);
    lsum0 += __shfl_xor_sync(0xffffffffu, lsum0, 2);
    lsum1 += __shfl_xor_sync(0xffffffffu, lsum1, 1);
    lsum1 += __shfl_xor_sync(0xffffffffu, lsum1, 2);
    const float inv0 = 1.f / lsum0;
    const float inv1 = 1.f / lsum1;

    const int row0 = bm0 + 16 * w + (lane >> 2);
    float* obase = out + (size_t)side * NQ * DV;
    const int coff = 2 * (lane & 3);
#pragma unroll
    for (int nt = 0; nt < 8; nt++) {
        float2 v0 = make_float2(fmaxf(o[nt][0] * inv0, 0.f), fmaxf(o[nt][1] * inv0, 0.f));
        float2 v1 = make_float2(fmaxf(o[nt][2] * inv1, 0.f), fmaxf(o[nt][3] * inv1, 0.f));
        *reinterpret_cast<float2*>(obase + (size_t)row0 * DV + 8 * nt + coff) = v0;
        *reinterpret_cast<float2*>(obase + (size_t)(row0 + 8) * DV + 8 * nt + coff) = v1;
    }
}

// ---------------------------------------------------------------------------
extern "C" void kernel_launch(void* const* d_in, const int* in_sizes, int n_in,
                              void* d_out, int out_size)
{
    (void)in_sizes; (void)n_in; (void)out_size;
    const float* review = (const float*)d_in[0];
    const float* user   = (const float*)d_in[1];
    const float* item   = (const float*)d_in[2];
    const int*   adj_ur = (const int*)d_in[3];
    const int*   adj_ri = (const int*)d_in[4];
    const int*   adj_ir = (const int*)d_in[5];
    const int*   adj_ru = (const int*)d_in[6];
    const float* Wu     = (const float*)d_in[7];
    const float* Wi     = (const float*)d_in[8];
    float* out = (float*)d_out;

    cudaFuncSetAttribute(build_v_kernel,
                         cudaFuncAttributeMaxDynamicSharedMemorySize, SMEM_BUILD);
    cudaFuncSetAttribute(flash_mma_kernel,
                         cudaFuncAttributeMaxDynamicSharedMemorySize, SMEM_FLASH);

    build_v_kernel<<<dim3(NQ / 32, 2), 256, SMEM_BUILD>>>(
        review, user, item, adj_ur, adj_ri, adj_ir, adj_ru, Wu, Wi);
    split_q_kernel<<<(2 * NQ * D + 255) / 256, 256>>>(user, item);
    split_v_kernel<<<dim3(NQ / 64, 2), 256>>>();

    dim3 grid(NQ / BM, 2);
    flash_mma_kernel<<<grid, 256, SMEM_FLASH>>>(out);
}

// round 9
// speedup vs baseline: 4.0368x; 1.1237x over previous
#include <cuda_runtime.h>
#include <cuda_bf16.h>
#include <cuda_fp16.h>
#include <cstdint>

#define NQ 8192
#define D 32
#define DV 64
#define KNB 4
#define IN_DIM 256

#define BM 64
#define BN 64
#define NITER (NQ / BN)   // 128
#define SBYTES 144        // 128B data + 16B pad per smem row

// ---------------- device scratch ----------------
__device__ __nv_bfloat16 g_Qs[2 * NQ * 64];   // [side][row][hi32|lo32] bf16
__device__ __half g_Vth[2 * DV * NQ];         // [side][n][j] fp16 hi
__device__ __half g_Vtl[2 * DV * NQ];         // [side][n][j] fp16 lo (residual)

// ---------------- PTX helpers ----------------
__device__ __forceinline__ uint32_t smem_u32(const void* p) {
    uint32_t a;
    asm("{ .reg .u64 t; cvta.to.shared.u64 t, %1; cvt.u32.u64 %0, t; }" : "=r"(a) : "l"(p));
    return a;
}
__device__ __forceinline__ void ldsm4(uint32_t r[4], uint32_t addr) {
    asm volatile("ldmatrix.sync.aligned.m8n8.x4.shared.b16 {%0,%1,%2,%3}, [%4];"
                 : "=r"(r[0]), "=r"(r[1]), "=r"(r[2]), "=r"(r[3]) : "r"(addr));
}
__device__ __forceinline__ void mma_bf16(float d[4], const uint32_t a[4], const uint32_t b[2]) {
    asm volatile(
        "mma.sync.aligned.m16n8k16.row.col.f32.bf16.bf16.f32 "
        "{%0,%1,%2,%3}, {%4,%5,%6,%7}, {%8,%9}, {%0,%1,%2,%3};"
        : "+f"(d[0]), "+f"(d[1]), "+f"(d[2]), "+f"(d[3])
        : "r"(a[0]), "r"(a[1]), "r"(a[2]), "r"(a[3]), "r"(b[0]), "r"(b[1]));
}
__device__ __forceinline__ void mma_fp16(float d[4], const uint32_t a[4], const uint32_t b[2]) {
    asm volatile(
        "mma.sync.aligned.m16n8k16.row.col.f32.f16.f16.f32 "
        "{%0,%1,%2,%3}, {%4,%5,%6,%7}, {%8,%9}, {%0,%1,%2,%3};"
        : "+f"(d[0]), "+f"(d[1]), "+f"(d[2]), "+f"(d[3])
        : "r"(a[0]), "r"(a[1]), "r"(a[2]), "r"(a[3]), "r"(b[0]), "r"(b[1]));
}
__device__ __forceinline__ float ex2f(float x) {
    float y; asm("ex2.approx.ftz.f32 %0, %1;" : "=f"(y) : "f"(x)); return y;
}
__device__ __forceinline__ uint32_t packh2(float a, float b) {
    __half2 h = __floats2half2_rn(a, b);
    return *reinterpret_cast<uint32_t*>(&h);
}
#define CP16(dst, src) \
    asm volatile("cp.async.cg.shared.global [%0], [%1], 16;" :: "r"(dst), "l"(src))
#define CP_COMMIT() asm volatile("cp.async.commit_group;" ::: "memory")
#define CP_WAIT1()  asm volatile("cp.async.wait_group 1;" ::: "memory")
#define CP_WAIT0()  asm volatile("cp.async.wait_group 0;" ::: "memory")

// flash smem layout (bytes) — BM=64
#define OFF_Q  0                    // 64 x 144 = 9216
#define OFF_K  9216                 // 2 bufs x 64 x 144
#define OFF_VH 27648                // 2 bufs
#define OFF_VL 46080                // 2 bufs
#define SMEM_FLASH 64512
#define BUF 9216

// ---------------------------------------------------------------------------
// Phase 1a (fused): V' = concat @ W, then split fp16 hi/lo + transpose, stored
// directly to g_Vth/g_Vtl.  64 users/block, 256 thr, thread = 2 users x 8 cols.
// ---------------------------------------------------------------------------
__global__ __launch_bounds__(256) void build_v_kernel(
    const float* __restrict__ review,
    const float* __restrict__ user, const float* __restrict__ item,
    const int* __restrict__ adj_ur, const int* __restrict__ adj_ri,
    const int* __restrict__ adj_ir, const int* __restrict__ adj_ru,
    const float* __restrict__ Wu, const float* __restrict__ Wi)
{
    extern __shared__ float sm[];                 // W[16384] | cat[64][256]
    float* Wsm = sm;
    float* cat = sm + IN_DIM * DV;

    const int side = blockIdx.y;
    const float* vecA = review;
    const int*   idxA = side ? adj_ir : adj_ur;
    const float* vecB = side ? user : item;
    const int*   idxB = side ? adj_ru : adj_ri;
    const float* W    = side ? Wi : Wu;

    const int tid = threadIdx.x;
    const int u0 = blockIdx.x * 64;

    // stage W (16384 floats = 4096 float4)
    for (int t = tid; t < IN_DIM * DV / 4; t += 256)
        reinterpret_cast<float4*>(Wsm)[t] = reinterpret_cast<const float4*>(W)[t];

    // gather 64 users x 256 feats
    for (int t = tid; t < 64 * IN_DIM; t += 256) {
        const int lu = t >> 8, pos = t & 255, k = pos >> 6, w = pos & 63;
        const int gu = u0 + lu;
        float v;
        if (w < 32) v = vecA[idxA[gu * KNB + k] * D + w];
        else        v = vecB[idxB[gu * KNB + k] * D + (w - 32)];
        cat[lu * IN_DIM + pos] = v;
    }
    __syncthreads();

    const int ug = tid >> 3;          // 0..31 -> users u0+2ug, u0+2ug+1
    const int cg = tid & 7;           // cols cg*8..+7
    const float* c0p = cat + (2 * ug) * IN_DIM;
    const float* c1p = cat + (2 * ug + 1) * IN_DIM;
    const float4* W4 = reinterpret_cast<const float4*>(Wsm);

    float a0[8], a1[8];
#pragma unroll
    for (int k = 0; k < 8; k++) { a0[k] = 0.f; a1[k] = 0.f; }

#pragma unroll 8
    for (int i = 0; i < IN_DIM; i++) {
        const float c0 = c0p[i];
        const float c1 = c1p[i];
        const float4 w0 = W4[i * 16 + cg * 2];
        const float4 w1 = W4[i * 16 + cg * 2 + 1];
        a0[0] += c0 * w0.x; a0[1] += c0 * w0.y; a0[2] += c0 * w0.z; a0[3] += c0 * w0.w;
        a0[4] += c0 * w1.x; a0[5] += c0 * w1.y; a0[6] += c0 * w1.z; a0[7] += c0 * w1.w;
        a1[0] += c1 * w0.x; a1[1] += c1 * w0.y; a1[2] += c1 * w0.z; a1[3] += c1 * w0.w;
        a1[4] += c1 * w1.x; a1[5] += c1 * w1.y; a1[6] += c1 * w1.z; a1[7] += c1 * w1.w;
    }

    // split fp16 hi/lo, store transposed [n][j] (j = u0+2ug even -> 4B aligned)
    __half2* Vh = reinterpret_cast<__half2*>(g_Vth + (size_t)side * DV * NQ);
    __half2* Vl = reinterpret_cast<__half2*>(g_Vtl + (size_t)side * DV * NQ);
    const int jh = (u0 + 2 * ug) >> 1;     // half2 index along j
#pragma unroll
    for (int k = 0; k < 8; k++) {
        const int n = cg * 8 + k;
        const __half h0 = __float2half_rn(a0[k]);
        const __half h1 = __float2half_rn(a1[k]);
        const float r0 = a0[k] - __half2float(h0);
        const float r1 = a1[k] - __half2float(h1);
        Vh[(size_t)n * (NQ / 2) + jh] = __half2(h0, h1);
        Vl[(size_t)n * (NQ / 2) + jh] = __half2(__float2half_rn(r0), __float2half_rn(r1));
    }
}
#define SMEM_BUILD ((IN_DIM * DV + 64 * IN_DIM) * 4)   // 128 KB

// ---------------------------------------------------------------------------
// Phase 1b: Q -> bf16 hi/lo, row layout [hi(0..31) | lo(0..31)]
// ---------------------------------------------------------------------------
__global__ __launch_bounds__(256) void split_q_kernel(
    const float* __restrict__ user_vecs, const float* __restrict__ item_vecs)
{
    int idx = blockIdx.x * 256 + threadIdx.x;
    if (idx >= 2 * NQ * D) return;
    int side = idx / (NQ * D);
    int r = idx % (NQ * D);
    int row = r >> 5, col = r & 31;
    const float* Q = side ? item_vecs : user_vecs;
    float x = Q[row * D + col];
    __nv_bfloat16 h = __float2bfloat16(x);
    float lo = x - __bfloat162float(h);
    __nv_bfloat16* dst = g_Qs + ((size_t)side * NQ + row) * 64;
    dst[col]      = h;
    dst[32 + col] = __float2bfloat16(lo);
}

// ---------------------------------------------------------------------------
// Phase 2: HMMA flash attention.  BM=64, 4 warps, 2 CTAs/SM for pipe overlap.
// QK: split-bf16 3 products; PV: P fp16 (biased exp), V fp16 hi+lo.
// ---------------------------------------------------------------------------
__global__ __launch_bounds__(128, 2) void flash_mma_kernel(float* __restrict__ out)
{
    extern __shared__ char smem[];
    const uint32_t sb = smem_u32(smem);
    const int tid = threadIdx.x;
    const int w = tid >> 5, lane = tid & 31;
    const int side = blockIdx.y;
    const int bm0 = blockIdx.x * BM;

    const __nv_bfloat16* Qside = g_Qs + (size_t)side * NQ * 64;
    const __half* VtH = g_Vth + (size_t)side * DV * NQ;
    const __half* VtL = g_Vtl + (size_t)side * DV * NQ;

    // Q tile: 64 rows x 8 chunks = 512 -> 4/thread
#pragma unroll
    for (int i = 0; i < 4; i++) {
        int t = tid + 128 * i;
        int r = t >> 3, seg = t & 7;
        CP16(sb + OFF_Q + r * SBYTES + seg * 16,
             Qside + (size_t)(bm0 + r) * 64 + seg * 8);
    }
    // tile 0 (K + VH + VL): 1536 chunks -> 12/thread
#pragma unroll
    for (int i = 0; i < 12; i++) {
        int t = tid + 128 * i;
        int arr = t >> 9, rem = t & 511;
        int r = rem >> 3, seg = rem & 7;
        if (arr == 0)
            CP16(sb + OFF_K + r * SBYTES + seg * 16, Qside + (size_t)r * 64 + seg * 8);
        else if (arr == 1)
            CP16(sb + OFF_VH + r * SBYTES + seg * 16, VtH + (size_t)r * NQ + seg * 8);
        else
            CP16(sb + OFF_VL + r * SBYTES + seg * 16, VtL + (size_t)r * NQ + seg * 8);
    }
    CP_COMMIT();

    uint32_t qh[2][4], ql[2][4];
    float o[8][4];
#pragma unroll
    for (int nt = 0; nt < 8; nt++)
#pragma unroll
        for (int i = 0; i < 4; i++) o[nt][i] = 0.f;
    float lsum0 = 0.f, lsum1 = 0.f;
    const float C  = 0.25503486f;    // log2(e)/sqrt(32)
    const float B2 = 11.5415603f;    // 8*log2(e)

    const int aRow = (lane & 7) + ((lane >> 3) & 1) * 8;
    const int aCol = ((lane >> 4) & 1) * 16;
    const int bRow = lane & 7;
    const int bCol = (lane >> 3) * 16;

    for (int it = 0; it < NITER; ++it) {
        const int cur = it & 1;
        if (it + 1 < NITER) {
            const int j0 = (it + 1) * BN;
            const int nb = (it + 1) & 1;
#pragma unroll
            for (int i = 0; i < 12; i++) {
                int t = tid + 128 * i;
                int arr = t >> 9, rem = t & 511;
                int r = rem >> 3, seg = rem & 7;
                if (arr == 0)
                    CP16(sb + OFF_K + nb * BUF + r * SBYTES + seg * 16,
                         Qside + (size_t)(j0 + r) * 64 + seg * 8);
                else if (arr == 1)
                    CP16(sb + OFF_VH + nb * BUF + r * SBYTES + seg * 16,
                         VtH + (size_t)r * NQ + j0 + seg * 8);
                else
                    CP16(sb + OFF_VL + nb * BUF + r * SBYTES + seg * 16,
                         VtL + (size_t)r * NQ + j0 + seg * 8);
            }
            CP_COMMIT();
            CP_WAIT1();
        } else {
            CP_WAIT0();
        }
        __syncthreads();

        if (it == 0) {
            const uint32_t qbase = sb + OFF_Q + (16 * w) * SBYTES + aRow * SBYTES + aCol;
            ldsm4(qh[0], qbase + 0);
            ldsm4(qh[1], qbase + 32);
            ldsm4(ql[0], qbase + 64);
            ldsm4(ql[1], qbase + 96);
        }

        // ---- S = Q K^T (split-bf16, 3 products) ----
        float s[8][4];
#pragma unroll
        for (int nt = 0; nt < 8; nt++)
#pragma unroll
            for (int i = 0; i < 4; i++) s[nt][i] = 0.f;

        const uint32_t kbase = sb + OFF_K + cur * BUF + bRow * SBYTES + bCol;
#pragma unroll
        for (int nt = 0; nt < 8; nt++) {
            uint32_t kh[4], kl[4];
            ldsm4(kh, kbase + (8 * nt) * SBYTES + 0);
            ldsm4(kl, kbase + (8 * nt) * SBYTES + 64);
            mma_bf16(s[nt], qh[0], kh + 0);
            mma_bf16(s[nt], qh[1], kh + 2);
            mma_bf16(s[nt], qh[0], kl + 0);
            mma_bf16(s[nt], qh[1], kl + 2);
            mma_bf16(s[nt], ql[0], kh + 0);
            mma_bf16(s[nt], ql[1], kh + 2);
        }

        // ---- exp (biased, unnormalized), row-sum, pack to fp16 frags ----
        float p[8][4];
#pragma unroll
        for (int nt = 0; nt < 8; nt++) {
#pragma unroll
            for (int i = 0; i < 4; i++) p[nt][i] = ex2f(s[nt][i] * C - B2);
            lsum0 += p[nt][0] + p[nt][1];
            lsum1 += p[nt][2] + p[nt][3];
        }
        uint32_t phi[4][4];
#pragma unroll
        for (int c = 0; c < 4; c++) {
#pragma unroll
            for (int h = 0; h < 4; h++) {
                const int nt = 2 * c + (h >> 1);
                phi[c][h] = packh2(p[nt][(h & 1) * 2 + 0], p[nt][(h & 1) * 2 + 1]);
            }
        }

        // ---- O += Ph @ (Vh + Vl) ----
        const uint32_t vhb = sb + OFF_VH + cur * BUF + bRow * SBYTES + bCol;
        const uint32_t vlb = sb + OFF_VL + cur * BUF + bRow * SBYTES + bCol;
#pragma unroll
        for (int nt = 0; nt < 8; nt++) {
            uint32_t vh[8], vl[8];
            ldsm4(vh + 0, vhb + (8 * nt) * SBYTES + 0);
            ldsm4(vh + 4, vhb + (8 * nt) * SBYTES + 64);
            ldsm4(vl + 0, vlb + (8 * nt) * SBYTES + 0);
            ldsm4(vl + 4, vlb + (8 * nt) * SBYTES + 64);
#pragma unroll
            for (int c = 0; c < 4; c++) {
                mma_fp16(o[nt], phi[c], vh + 2 * c);
                mma_fp16(o[nt], phi[c], vl + 2 * c);
            }
        }
        __syncthreads();
    }

    // ---- epilogue ----
    lsum0 += __shfl_xor_sync(0xffffffffu, lsum0, 1);
    lsum0 += __shfl_xor_sync(0xffffffffu, lsum0, 2);
    lsum1 += __shfl_xor_sync(0xffffffffu, lsum1, 1);
    lsum1 += __shfl_xor_sync(0xffffffffu, lsum1, 2);
    const float inv0 = 1.f / lsum0;
    const float inv1 = 1.f / lsum1;

    const int row0 = bm0 + 16 * w + (lane >> 2);
    float* obase = out + (size_t)side * NQ * DV;
    const int coff = 2 * (lane & 3);
#pragma unroll
    for (int nt = 0; nt < 8; nt++) {
        float2 v0 = make_float2(fmaxf(o[nt][0] * inv0, 0.f), fmaxf(o[nt][1] * inv0, 0.f));
        float2 v1 = make_float2(fmaxf(o[nt][2] * inv1, 0.f), fmaxf(o[nt][3] * inv1, 0.f));
        *reinterpret_cast<float2*>(obase + (size_t)row0 * DV + 8 * nt + coff) = v0;
        *reinterpret_cast<float2*>(obase + (size_t)(row0 + 8) * DV + 8 * nt + coff) = v1;
    }
}

// ---------------------------------------------------------------------------
extern "C" void kernel_launch(void* const* d_in, const int* in_sizes, int n_in,
                              void* d_out, int out_size)
{
    (void)in_sizes; (void)n_in; (void)out_size;
    const float* review = (const float*)d_in[0];
    const float* user   = (const float*)d_in[1];
    const float* item   = (const float*)d_in[2];
    const int*   adj_ur = (const int*)d_in[3];
    const int*   adj_ri = (const int*)d_in[4];
    const int*   adj_ir = (const int*)d_in[5];
    const int*   adj_ru = (const int*)d_in[6];
    const float* Wu     = (const float*)d_in[7];
    const float* Wi     = (const float*)d_in[8];
    float* out = (float*)d_out;

    cudaFuncSetAttribute(build_v_kernel,
                         cudaFuncAttributeMaxDynamicSharedMemorySize, SMEM_BUILD);
    cudaFuncSetAttribute(flash_mma_kernel,
                         cudaFuncAttributeMaxDynamicSharedMemorySize, SMEM_FLASH);

    build_v_kernel<<<dim3(NQ / 64, 2), 256, SMEM_BUILD>>>(
        review, user, item, adj_ur, adj_ri, adj_ir, adj_ru, Wu, Wi);
    split_q_kernel<<<(2 * NQ * D + 255) / 256, 256>>>(user, item);

    dim3 grid(NQ / BM, 2);
    flash_mma_kernel<<<grid, 128, SMEM_FLASH>>>(out);
}

// round 10
// speedup vs baseline: 4.7248x; 1.1704x over previous
#include <cuda_runtime.h>
#include <cuda_bf16.h>
#include <cuda_fp16.h>
#include <cstdint>

#define NQ 8192
#define D 32
#define DV 64
#define KNB 4
#define IN_DIM 256

#define BM 64
#define BN 64
#define NITER (NQ / BN)   // 128
#define SBYTES 144        // 128B data + 16B pad per smem row

// ---------------- device scratch ----------------
__device__ __nv_bfloat16 g_Qs[2 * NQ * 64];   // [side][row][hi32|lo32] bf16
__device__ __half g_Vth[2 * DV * NQ];         // [side][n][j] fp16

// ---------------- PTX helpers ----------------
__device__ __forceinline__ uint32_t smem_u32(const void* p) {
    uint32_t a;
    asm("{ .reg .u64 t; cvta.to.shared.u64 t, %1; cvt.u32.u64 %0, t; }" : "=r"(a) : "l"(p));
    return a;
}
__device__ __forceinline__ void ldsm4(uint32_t r[4], uint32_t addr) {
    asm volatile("ldmatrix.sync.aligned.m8n8.x4.shared.b16 {%0,%1,%2,%3}, [%4];"
                 : "=r"(r[0]), "=r"(r[1]), "=r"(r[2]), "=r"(r[3]) : "r"(addr));
}
__device__ __forceinline__ void mma_bf16(float d[4], const uint32_t a[4], const uint32_t b[2]) {
    asm volatile(
        "mma.sync.aligned.m16n8k16.row.col.f32.bf16.bf16.f32 "
        "{%0,%1,%2,%3}, {%4,%5,%6,%7}, {%8,%9}, {%0,%1,%2,%3};"
        : "+f"(d[0]), "+f"(d[1]), "+f"(d[2]), "+f"(d[3])
        : "r"(a[0]), "r"(a[1]), "r"(a[2]), "r"(a[3]), "r"(b[0]), "r"(b[1]));
}
__device__ __forceinline__ void mma_fp16(float d[4], const uint32_t a[4], const uint32_t b[2]) {
    asm volatile(
        "mma.sync.aligned.m16n8k16.row.col.f32.f16.f16.f32 "
        "{%0,%1,%2,%3}, {%4,%5,%6,%7}, {%8,%9}, {%0,%1,%2,%3};"
        : "+f"(d[0]), "+f"(d[1]), "+f"(d[2]), "+f"(d[3])
        : "r"(a[0]), "r"(a[1]), "r"(a[2]), "r"(a[3]), "r"(b[0]), "r"(b[1]));
}
__device__ __forceinline__ float ex2f(float x) {
    float y; asm("ex2.approx.ftz.f32 %0, %1;" : "=f"(y) : "f"(x)); return y;
}
__device__ __forceinline__ uint32_t packh2(float a, float b) {
    __half2 h = __floats2half2_rn(a, b);
    return *reinterpret_cast<uint32_t*>(&h);
}
#define CP16(dst, src) \
    asm volatile("cp.async.cg.shared.global [%0], [%1], 16;" :: "r"(dst), "l"(src))
#define CP_COMMIT() asm volatile("cp.async.commit_group;" ::: "memory")
#define CP_WAIT1()  asm volatile("cp.async.wait_group 1;" ::: "memory")
#define CP_WAIT0()  asm volatile("cp.async.wait_group 0;" ::: "memory")

// flash smem layout (bytes) — BM=64, single V plane
#define OFF_Q  0                    // 64 x 144 = 9216
#define OFF_K  9216                 // 2 bufs x 64 x 144
#define OFF_VH 27648                // 2 bufs x 64 x 144
#define SMEM_FLASH 46080
#define BUF 9216

// ---------------------------------------------------------------------------
// Phase 1a (fused): V' = concat @ W -> fp16, transposed [n][j].
// 64 users/block, 512 threads (thread = 1 user x 8 cols), W staged in smem.
// ---------------------------------------------------------------------------
__global__ __launch_bounds__(512) void build_v_kernel(
    const float* __restrict__ review,
    const float* __restrict__ user, const float* __restrict__ item,
    const int* __restrict__ adj_ur, const int* __restrict__ adj_ri,
    const int* __restrict__ adj_ir, const int* __restrict__ adj_ru,
    const float* __restrict__ Wu, const float* __restrict__ Wi)
{
    extern __shared__ float sm[];                 // W[16384] | cat[64][256]
    float* Wsm = sm;
    float* cat = sm + IN_DIM * DV;

    const int side = blockIdx.y;
    const float* vecA = review;
    const int*   idxA = side ? adj_ir : adj_ur;
    const float* vecB = side ? user : item;
    const int*   idxB = side ? adj_ru : adj_ri;
    const float* W    = side ? Wi : Wu;

    const int tid = threadIdx.x;
    const int u0 = blockIdx.x * 64;

    // stage W (4096 float4)
    for (int t = tid; t < IN_DIM * DV / 4; t += 512)
        reinterpret_cast<float4*>(Wsm)[t] = reinterpret_cast<const float4*>(W)[t];

    // gather 64 users x 256 feats
    for (int t = tid; t < 64 * IN_DIM; t += 512) {
        const int lu = t >> 8, pos = t & 255, k = pos >> 6, w = pos & 63;
        const int gu = u0 + lu;
        float v;
        if (w < 32) v = vecA[idxA[gu * KNB + k] * D + w];
        else        v = vecB[idxB[gu * KNB + k] * D + (w - 32)];
        cat[lu * IN_DIM + pos] = v;
    }
    __syncthreads();

    const int u  = tid >> 3;          // 0..63
    const int cg = tid & 7;           // cols cg*8..+7
    const float* cp = cat + u * IN_DIM;
    const float4* W4 = reinterpret_cast<const float4*>(Wsm);

    float a0[8];
#pragma unroll
    for (int k = 0; k < 8; k++) a0[k] = 0.f;

#pragma unroll 8
    for (int i = 0; i < IN_DIM; i++) {
        const float c = cp[i];
        const float4 w0 = W4[i * 16 + cg * 2];
        const float4 w1 = W4[i * 16 + cg * 2 + 1];
        a0[0] += c * w0.x; a0[1] += c * w0.y; a0[2] += c * w0.z; a0[3] += c * w0.w;
        a0[4] += c * w1.x; a0[5] += c * w1.y; a0[6] += c * w1.z; a0[7] += c * w1.w;
    }

    // store fp16, transposed [n][j]
    __half* Vh = g_Vth + (size_t)side * DV * NQ;
    const int j = u0 + u;
#pragma unroll
    for (int k = 0; k < 8; k++) {
        const int n = cg * 8 + k;
        Vh[(size_t)n * NQ + j] = __float2half_rn(a0[k]);
    }
}
#define SMEM_BUILD ((IN_DIM * DV + 64 * IN_DIM) * 4)   // 128 KB

// ---------------------------------------------------------------------------
// Phase 1b: Q -> bf16 hi/lo, row layout [hi(0..31) | lo(0..31)]
// ---------------------------------------------------------------------------
__global__ __launch_bounds__(256) void split_q_kernel(
    const float* __restrict__ user_vecs, const float* __restrict__ item_vecs)
{
    int idx = blockIdx.x * 256 + threadIdx.x;
    if (idx >= 2 * NQ * D) return;
    int side = idx / (NQ * D);
    int r = idx % (NQ * D);
    int row = r >> 5, col = r & 31;
    const float* Q = side ? item_vecs : user_vecs;
    float x = Q[row * D + col];
    __nv_bfloat16 h = __float2bfloat16(x);
    float lo = x - __bfloat162float(h);
    __nv_bfloat16* dst = g_Qs + ((size_t)side * NQ + row) * 64;
    dst[col]      = h;
    dst[32 + col] = __float2bfloat16(lo);
}

// ---------------------------------------------------------------------------
// Phase 2: HMMA flash attention.  BM=64, 4 warps, 2 CTAs/SM.
// QK: split-bf16 3 products; PV: P fp16 (biased exp), V fp16 single.
// ---------------------------------------------------------------------------
__global__ __launch_bounds__(128, 2) void flash_mma_kernel(float* __restrict__ out)
{
    extern __shared__ char smem[];
    const uint32_t sb = smem_u32(smem);
    const int tid = threadIdx.x;
    const int w = tid >> 5, lane = tid & 31;
    const int side = blockIdx.y;
    const int bm0 = blockIdx.x * BM;

    const __nv_bfloat16* Qside = g_Qs + (size_t)side * NQ * 64;
    const __half* VtH = g_Vth + (size_t)side * DV * NQ;

    // Q tile: 512 chunks -> 4/thread
#pragma unroll
    for (int i = 0; i < 4; i++) {
        int t = tid + 128 * i;
        int r = t >> 3, seg = t & 7;
        CP16(sb + OFF_Q + r * SBYTES + seg * 16,
             Qside + (size_t)(bm0 + r) * 64 + seg * 8);
    }
    // tile 0 (K + VH): 1024 chunks -> 8/thread
#pragma unroll
    for (int i = 0; i < 8; i++) {
        int t = tid + 128 * i;
        int arr = t >> 9, rem = t & 511;
        int r = rem >> 3, seg = rem & 7;
        if (arr == 0)
            CP16(sb + OFF_K + r * SBYTES + seg * 16, Qside + (size_t)r * 64 + seg * 8);
        else
            CP16(sb + OFF_VH + r * SBYTES + seg * 16, VtH + (size_t)r * NQ + seg * 8);
    }
    CP_COMMIT();

    uint32_t qh[2][4], ql[2][4];
    float o[8][4];
#pragma unroll
    for (int nt = 0; nt < 8; nt++)
#pragma unroll
        for (int i = 0; i < 4; i++) o[nt][i] = 0.f;
    float lsum0 = 0.f, lsum1 = 0.f;
    const float C  = 0.25503486f;    // log2(e)/sqrt(32)
    const float B2 = 11.5415603f;    // 8*log2(e)

    const int aRow = (lane & 7) + ((lane >> 3) & 1) * 8;
    const int aCol = ((lane >> 4) & 1) * 16;
    const int bRow = lane & 7;
    const int bCol = (lane >> 3) * 16;

    for (int it = 0; it < NITER; ++it) {
        const int cur = it & 1;
        if (it + 1 < NITER) {
            const int j0 = (it + 1) * BN;
            const int nb = (it + 1) & 1;
#pragma unroll
            for (int i = 0; i < 8; i++) {
                int t = tid + 128 * i;
                int arr = t >> 9, rem = t & 511;
                int r = rem >> 3, seg = rem & 7;
                if (arr == 0)
                    CP16(sb + OFF_K + nb * BUF + r * SBYTES + seg * 16,
                         Qside + (size_t)(j0 + r) * 64 + seg * 8);
                else
                    CP16(sb + OFF_VH + nb * BUF + r * SBYTES + seg * 16,
                         VtH + (size_t)r * NQ + j0 + seg * 8);
            }
            CP_COMMIT();
            CP_WAIT1();
        } else {
            CP_WAIT0();
        }
        __syncthreads();

        if (it == 0) {
            const uint32_t qbase = sb + OFF_Q + (16 * w) * SBYTES + aRow * SBYTES + aCol;
            ldsm4(qh[0], qbase + 0);
            ldsm4(qh[1], qbase + 32);
            ldsm4(ql[0], qbase + 64);
            ldsm4(ql[1], qbase + 96);
        }

        // ---- S = Q K^T (split-bf16, 3 products) ----
        float s[8][4];
#pragma unroll
        for (int nt = 0; nt < 8; nt++)
#pragma unroll
            for (int i = 0; i < 4; i++) s[nt][i] = 0.f;

        const uint32_t kbase = sb + OFF_K + cur * BUF + bRow * SBYTES + bCol;
#pragma unroll
        for (int nt = 0; nt < 8; nt++) {
            uint32_t kh[4], kl[4];
            ldsm4(kh, kbase + (8 * nt) * SBYTES + 0);
            ldsm4(kl, kbase + (8 * nt) * SBYTES + 64);
            mma_bf16(s[nt], qh[0], kh + 0);
            mma_bf16(s[nt], qh[1], kh + 2);
            mma_bf16(s[nt], qh[0], kl + 0);
            mma_bf16(s[nt], qh[1], kl + 2);
            mma_bf16(s[nt], ql[0], kh + 0);
            mma_bf16(s[nt], ql[1], kh + 2);
        }

        // ---- exp (biased, unnormalized), row-sum, pack to fp16 frags ----
        float p[8][4];
#pragma unroll
        for (int nt = 0; nt < 8; nt++) {
#pragma unroll
            for (int i = 0; i < 4; i++) p[nt][i] = ex2f(s[nt][i] * C - B2);
            lsum0 += p[nt][0] + p[nt][1];
            lsum1 += p[nt][2] + p[nt][3];
        }
        uint32_t phi[4][4];
#pragma unroll
        for (int c = 0; c < 4; c++) {
#pragma unroll
            for (int h = 0; h < 4; h++) {
                const int nt = 2 * c + (h >> 1);
                phi[c][h] = packh2(p[nt][(h & 1) * 2 + 0], p[nt][(h & 1) * 2 + 1]);
            }
        }

        // ---- O += Ph @ Vh ----
        const uint32_t vhb = sb + OFF_VH + cur * BUF + bRow * SBYTES + bCol;
#pragma unroll
        for (int nt = 0; nt < 8; nt++) {
            uint32_t vh[8];
            ldsm4(vh + 0, vhb + (8 * nt) * SBYTES + 0);
            ldsm4(vh + 4, vhb + (8 * nt) * SBYTES + 64);
#pragma unroll
            for (int c = 0; c < 4; c++)
                mma_fp16(o[nt], phi[c], vh + 2 * c);
        }
        __syncthreads();
    }

    // ---- epilogue ----
    lsum0 += __shfl_xor_sync(0xffffffffu, lsum0, 1);
    lsum0 += __shfl_xor_sync(0xffffffffu, lsum0, 2);
    lsum1 += __shfl_xor_sync(0xffffffffu, lsum1, 1);
    lsum1 += __shfl_xor_sync(0xffffffffu, lsum1, 2);
    const float inv0 = 1.f / lsum0;
    const float inv1 = 1.f / lsum1;

    const int row0 = bm0 + 16 * w + (lane >> 2);
    float* obase = out + (size_t)side * NQ * DV;
    const int coff = 2 * (lane & 3);
#pragma unroll
    for (int nt = 0; nt < 8; nt++) {
        float2 v0 = make_float2(fmaxf(o[nt][0] * inv0, 0.f), fmaxf(o[nt][1] * inv0, 0.f));
        float2 v1 = make_float2(fmaxf(o[nt][2] * inv1, 0.f), fmaxf(o[nt][3] * inv1, 0.f));
        *reinterpret_cast<float2*>(obase + (size_t)row0 * DV + 8 * nt + coff) = v0;
        *reinterpret_cast<float2*>(obase + (size_t)(row0 + 8) * DV + 8 * nt + coff) = v1;
    }
}

// ---------------------------------------------------------------------------
extern "C" void kernel_launch(void* const* d_in, const int* in_sizes, int n_in,
                              void* d_out, int out_size)
{
    (void)in_sizes; (void)n_in; (void)out_size;
    const float* review = (const float*)d_in[0];
    const float* user   = (const float*)d_in[1];
    const float* item   = (const float*)d_in[2];
    const int*   adj_ur = (const int*)d_in[3];
    const int*   adj_ri = (const int*)d_in[4];
    const int*   adj_ir = (const int*)d_in[5];
    const int*   adj_ru = (const int*)d_in[6];
    const float* Wu     = (const float*)d_in[7];
    const float* Wi     = (const float*)d_in[8];
    float* out = (float*)d_out;

    cudaFuncSetAttribute(build_v_kernel,
                         cudaFuncAttributeMaxDynamicSharedMemorySize, SMEM_BUILD);
    cudaFuncSetAttribute(flash_mma_kernel,
                         cudaFuncAttributeMaxDynamicSharedMemorySize, SMEM_FLASH);

    build_v_kernel<<<dim3(NQ / 64, 2), 512, SMEM_BUILD>>>(
        review, user, item, adj_ur, adj_ri, adj_ir, adj_ru, Wu, Wi);
    split_q_kernel<<<(2 * NQ * D + 255) / 256, 256>>>(user, item);

    dim3 grid(NQ / BM, 2);
    flash_mma_kernel<<<grid, 128, SMEM_FLASH>>>(out);
}

// round 11
// speedup vs baseline: 6.2950x; 1.3323x over previous
#include <cuda_runtime.h>
#include <cuda_bf16.h>
#include <cuda_fp16.h>
#include <cstdint>

#define NQ 8192
#define D 32
#define DV 64
#define KNB 4
#define IN_DIM 256

#define BM 64
#define BN 64
#define NITER (NQ / BN)   // 128
#define SBYTES 144        // 128B data + 16B pad per smem row

// ---------------- device scratch ----------------
__device__ __nv_bfloat16 g_Qs[2 * NQ * 64];   // [side][row][hi32|lo32] bf16
__device__ __half g_Vth[2 * DV * NQ];         // [side][n][j] fp16

// ---------------- PTX helpers ----------------
__device__ __forceinline__ uint32_t smem_u32(const void* p) {
    uint32_t a;
    asm("{ .reg .u64 t; cvta.to.shared.u64 t, %1; cvt.u32.u64 %0, t; }" : "=r"(a) : "l"(p));
    return a;
}
__device__ __forceinline__ void ldsm4(uint32_t r[4], uint32_t addr) {
    asm volatile("ldmatrix.sync.aligned.m8n8.x4.shared.b16 {%0,%1,%2,%3}, [%4];"
                 : "=r"(r[0]), "=r"(r[1]), "=r"(r[2]), "=r"(r[3]) : "r"(addr));
}
__device__ __forceinline__ void mma_bf16(float d[4], const uint32_t a[4], const uint32_t b[2]) {
    asm volatile(
        "mma.sync.aligned.m16n8k16.row.col.f32.bf16.bf16.f32 "
        "{%0,%1,%2,%3}, {%4,%5,%6,%7}, {%8,%9}, {%0,%1,%2,%3};"
        : "+f"(d[0]), "+f"(d[1]), "+f"(d[2]), "+f"(d[3])
        : "r"(a[0]), "r"(a[1]), "r"(a[2]), "r"(a[3]), "r"(b[0]), "r"(b[1]));
}
__device__ __forceinline__ void mma_fp16(float d[4], const uint32_t a[4], const uint32_t b[2]) {
    asm volatile(
        "mma.sync.aligned.m16n8k16.row.col.f32.f16.f16.f32 "
        "{%0,%1,%2,%3}, {%4,%5,%6,%7}, {%8,%9}, {%0,%1,%2,%3};"
        : "+f"(d[0]), "+f"(d[1]), "+f"(d[2]), "+f"(d[3])
        : "r"(a[0]), "r"(a[1]), "r"(a[2]), "r"(a[3]), "r"(b[0]), "r"(b[1]));
}
__device__ __forceinline__ float ex2f(float x) {
    float y; asm("ex2.approx.ftz.f32 %0, %1;" : "=f"(y) : "f"(x)); return y;
}
__device__ __forceinline__ uint32_t packh2(float a, float b) {
    __half2 h = __floats2half2_rn(a, b);
    return *reinterpret_cast<uint32_t*>(&h);
}
#define CP16(dst, src) \
    asm volatile("cp.async.cg.shared.global [%0], [%1], 16;" :: "r"(dst), "l"(src))
#define CP_COMMIT() asm volatile("cp.async.commit_group;" ::: "memory")
#define CP_WAIT1()  asm volatile("cp.async.wait_group 1;" ::: "memory")
#define CP_WAIT0()  asm volatile("cp.async.wait_group 0;" ::: "memory")

// flash smem layout (bytes) — BM=64, single V plane
#define OFF_Q  0                    // 64 x 144 = 9216
#define OFF_K  9216                 // 2 bufs x 64 x 144
#define OFF_VH 27648                // 2 bufs x 64 x 144
#define SMEM_FLASH 46080
#define BUF 9216

// ---------------------------------------------------------------------------
// Phase 1 (fused): blocks [0,128): V' = concat @ W -> fp16 transposed [n][j].
//                  blocks [128,144): split Q -> bf16 hi/lo rows.
// V' GEMM: 256 thr, 64 users/block, thread = 4 users x 4 cols.
// W read via __ldg (L1-resident 64 KB); cat in 64 KB dynamic smem -> 2 CTAs/SM.
// ---------------------------------------------------------------------------
__global__ __launch_bounds__(256, 2) void build_v_kernel(
    const float* __restrict__ review,
    const float* __restrict__ user, const float* __restrict__ item,
    const int* __restrict__ adj_ur, const int* __restrict__ adj_ri,
    const int* __restrict__ adj_ir, const int* __restrict__ adj_ru,
    const float* __restrict__ Wu, const float* __restrict__ Wi)
{
    const int side = blockIdx.y;
    const int tid = threadIdx.x;

    if (blockIdx.x >= NQ / 64) {
        // ---- split_q part: 512 rows per block ----
        const float* Q = side ? item : user;
        const int rbase = (blockIdx.x - NQ / 64) * 512;
#pragma unroll
        for (int rr = 0; rr < 2; rr++) {
            const int row = rbase + tid + rr * 256;
            const float4* src = reinterpret_cast<const float4*>(Q + (size_t)row * D);
            __nv_bfloat16* dst = g_Qs + ((size_t)side * NQ + row) * 64;
            __nv_bfloat162* dh = reinterpret_cast<__nv_bfloat162*>(dst);
            __nv_bfloat162* dl = reinterpret_cast<__nv_bfloat162*>(dst + 32);
#pragma unroll
            for (int s = 0; s < 8; s++) {
                const float4 v = __ldg(src + s);
                const __nv_bfloat16 h0 = __float2bfloat16(v.x);
                const __nv_bfloat16 h1 = __float2bfloat16(v.y);
                const __nv_bfloat16 h2 = __float2bfloat16(v.z);
                const __nv_bfloat16 h3 = __float2bfloat16(v.w);
                dh[s * 2 + 0] = __nv_bfloat162(h0, h1);
                dh[s * 2 + 1] = __nv_bfloat162(h2, h3);
                dl[s * 2 + 0] = __nv_bfloat162(
                    __float2bfloat16(v.x - __bfloat162float(h0)),
                    __float2bfloat16(v.y - __bfloat162float(h1)));
                dl[s * 2 + 1] = __nv_bfloat162(
                    __float2bfloat16(v.z - __bfloat162float(h2)),
                    __float2bfloat16(v.w - __bfloat162float(h3)));
            }
        }
        return;
    }

    // ---- V' GEMM part ----
    extern __shared__ float cat[];                // [64][IN_DIM] = 64 KB
    const float* vecA = review;
    const int*   idxA = side ? adj_ir : adj_ur;
    const float* vecB = side ? user : item;
    const int*   idxB = side ? adj_ru : adj_ri;
    const float* W    = side ? Wi : Wu;
    const int u0 = blockIdx.x * 64;

    // gather 64 users x 256 feats
    for (int t = tid; t < 64 * IN_DIM; t += 256) {
        const int lu = t >> 8, pos = t & 255, k = pos >> 6, w = pos & 63;
        const int gu = u0 + lu;
        float v;
        if (w < 32) v = vecA[idxA[gu * KNB + k] * D + w];
        else        v = vecB[idxB[gu * KNB + k] * D + (w - 32)];
        cat[lu * IN_DIM + pos] = v;
    }
    __syncthreads();

    const int cg  = tid & 15;          // col group: cols cg*4..+3
    const int ugb = (tid >> 4) * 4;    // users ugb..ugb+3
    const float4* Wg = reinterpret_cast<const float4*>(W);
    const float* c0 = cat + (ugb + 0) * IN_DIM;
    const float* c1 = cat + (ugb + 1) * IN_DIM;
    const float* c2 = cat + (ugb + 2) * IN_DIM;
    const float* c3 = cat + (ugb + 3) * IN_DIM;

    float a0[4], a1[4], a2[4], a3[4];
#pragma unroll
    for (int k = 0; k < 4; k++) { a0[k] = 0.f; a1[k] = 0.f; a2[k] = 0.f; a3[k] = 0.f; }

#pragma unroll 8
    for (int i = 0; i < IN_DIM; i++) {
        const float4 wv = __ldg(&Wg[i * 16 + cg]);
        const float v0 = c0[i], v1 = c1[i], v2 = c2[i], v3 = c3[i];
        a0[0] += v0 * wv.x; a0[1] += v0 * wv.y; a0[2] += v0 * wv.z; a0[3] += v0 * wv.w;
        a1[0] += v1 * wv.x; a1[1] += v1 * wv.y; a1[2] += v1 * wv.z; a1[3] += v1 * wv.w;
        a2[0] += v2 * wv.x; a2[1] += v2 * wv.y; a2[2] += v2 * wv.z; a2[3] += v2 * wv.w;
        a3[0] += v3 * wv.x; a3[1] += v3 * wv.y; a3[2] += v3 * wv.z; a3[3] += v3 * wv.w;
    }

    // store fp16 transposed [n][j]; consecutive users -> half2 packs
    __half2* Vh = reinterpret_cast<__half2*>(g_Vth + (size_t)side * DV * NQ);
    const int jh = (u0 + ugb) >> 1;
#pragma unroll
    for (int k = 0; k < 4; k++) {
        const int n = cg * 4 + k;
        Vh[(size_t)n * (NQ / 2) + jh]     = __floats2half2_rn(a0[k], a1[k]);
        Vh[(size_t)n * (NQ / 2) + jh + 1] = __floats2half2_rn(a2[k], a3[k]);
    }
}
#define SMEM_BUILD (64 * IN_DIM * 4)   // 64 KB

// ---------------------------------------------------------------------------
// Phase 2: HMMA flash attention.  BM=64, 4 warps, 2 CTAs/SM.  (unchanged)
// QK: split-bf16 3 products; PV: P fp16 (biased exp), V fp16 single.
// ---------------------------------------------------------------------------
__global__ __launch_bounds__(128, 2) void flash_mma_kernel(float* __restrict__ out)
{
    extern __shared__ char smem[];
    const uint32_t sb = smem_u32(smem);
    const int tid = threadIdx.x;
    const int w = tid >> 5, lane = tid & 31;
    const int side = blockIdx.y;
    const int bm0 = blockIdx.x * BM;

    const __nv_bfloat16* Qside = g_Qs + (size_t)side * NQ * 64;
    const __half* VtH = g_Vth + (size_t)side * DV * NQ;

#pragma unroll
    for (int i = 0; i < 4; i++) {
        int t = tid + 128 * i;
        int r = t >> 3, seg = t & 7;
        CP16(sb + OFF_Q + r * SBYTES + seg * 16,
             Qside + (size_t)(bm0 + r) * 64 + seg * 8);
    }
#pragma unroll
    for (int i = 0; i < 8; i++) {
        int t = tid + 128 * i;
        int arr = t >> 9, rem = t & 511;
        int r = rem >> 3, seg = rem & 7;
        if (arr == 0)
            CP16(sb + OFF_K + r * SBYTES + seg * 16, Qside + (size_t)r * 64 + seg * 8);
        else
            CP16(sb + OFF_VH + r * SBYTES + seg * 16, VtH + (size_t)r * NQ + seg * 8);
    }
    CP_COMMIT();

    uint32_t qh[2][4], ql[2][4];
    float o[8][4];
#pragma unroll
    for (int nt = 0; nt < 8; nt++)
#pragma unroll
        for (int i = 0; i < 4; i++) o[nt][i] = 0.f;
    float lsum0 = 0.f, lsum1 = 0.f;
    const float C  = 0.25503486f;    // log2(e)/sqrt(32)
    const float B2 = 11.5415603f;    // 8*log2(e)

    const int aRow = (lane & 7) + ((lane >> 3) & 1) * 8;
    const int aCol = ((lane >> 4) & 1) * 16;
    const int bRow = lane & 7;
    const int bCol = (lane >> 3) * 16;

    for (int it = 0; it < NITER; ++it) {
        const int cur = it & 1;
        if (it + 1 < NITER) {
            const int j0 = (it + 1) * BN;
            const int nb = (it + 1) & 1;
#pragma unroll
            for (int i = 0; i < 8; i++) {
                int t = tid + 128 * i;
                int arr = t >> 9, rem = t & 511;
                int r = rem >> 3, seg = rem & 7;
                if (arr == 0)
                    CP16(sb + OFF_K + nb * BUF + r * SBYTES + seg * 16,
                         Qside + (size_t)(j0 + r) * 64 + seg * 8);
                else
                    CP16(sb + OFF_VH + nb * BUF + r * SBYTES + seg * 16,
                         VtH + (size_t)r * NQ + j0 + seg * 8);
            }
            CP_COMMIT();
            CP_WAIT1();
        } else {
            CP_WAIT0();
        }
        __syncthreads();

        if (it == 0) {
            const uint32_t qbase = sb + OFF_Q + (16 * w) * SBYTES + aRow * SBYTES + aCol;
            ldsm4(qh[0], qbase + 0);
            ldsm4(qh[1], qbase + 32);
            ldsm4(ql[0], qbase + 64);
            ldsm4(ql[1], qbase + 96);
        }

        float s[8][4];
#pragma unroll
        for (int nt = 0; nt < 8; nt++)
#pragma unroll
            for (int i = 0; i < 4; i++) s[nt][i] = 0.f;

        const uint32_t kbase = sb + OFF_K + cur * BUF + bRow * SBYTES + bCol;
#pragma unroll
        for (int nt = 0; nt < 8; nt++) {
            uint32_t kh[4], kl[4];
            ldsm4(kh, kbase + (8 * nt) * SBYTES + 0);
            ldsm4(kl, kbase + (8 * nt) * SBYTES + 64);
            mma_bf16(s[nt], qh[0], kh + 0);
            mma_bf16(s[nt], qh[1], kh + 2);
            mma_bf16(s[nt], qh[0], kl + 0);
            mma_bf16(s[nt], qh[1], kl + 2);
            mma_bf16(s[nt], ql[0], kh + 0);
            mma_bf16(s[nt], ql[1], kh + 2);
        }

        float p[8][4];
#pragma unroll
        for (int nt = 0; nt < 8; nt++) {
#pragma unroll
            for (int i = 0; i < 4; i++) p[nt][i] = ex2f(s[nt][i] * C - B2);
            lsum0 += p[nt][0] + p[nt][1];
            lsum1 += p[nt][2] + p[nt][3];
        }
        uint32_t phi[4][4];
#pragma unroll
        for (int c = 0; c < 4; c++) {
#pragma unroll
            for (int h = 0; h < 4; h++) {
                const int nt = 2 * c + (h >> 1);
                phi[c][h] = packh2(p[nt][(h & 1) * 2 + 0], p[nt][(h & 1) * 2 + 1]);
            }
        }

        const uint32_t vhb = sb + OFF_VH + cur * BUF + bRow * SBYTES + bCol;
#pragma unroll
        for (int nt = 0; nt < 8; nt++) {
            uint32_t vh[8];
            ldsm4(vh + 0, vhb + (8 * nt) * SBYTES + 0);
            ldsm4(vh + 4, vhb + (8 * nt) * SBYTES + 64);
#pragma unroll
            for (int c = 0; c < 4; c++)
                mma_fp16(o[nt], phi[c], vh + 2 * c);
        }
        __syncthreads();
    }

    lsum0 += __shfl_xor_sync(0xffffffffu, lsum0, 1);
    lsum0 += __shfl_xor_sync(0xffffffffu, lsum0, 2);
    lsum1 += __shfl_xor_sync(0xffffffffu, lsum1, 1);
    lsum1 += __shfl_xor_sync(0xffffffffu, lsum1, 2);
    const float inv0 = 1.f / lsum0;
    const float inv1 = 1.f / lsum1;

    const int row0 = bm0 + 16 * w + (lane >> 2);
    float* obase = out + (size_t)side * NQ * DV;
    const int coff = 2 * (lane & 3);
#pragma unroll
    for (int nt = 0; nt < 8; nt++) {
        float2 v0 = make_float2(fmaxf(o[nt][0] * inv0, 0.f), fmaxf(o[nt][1] * inv0, 0.f));
        float2 v1 = make_float2(fmaxf(o[nt][2] * inv1, 0.f), fmaxf(o[nt][3] * inv1, 0.f));
        *reinterpret_cast<float2*>(obase + (size_t)row0 * DV + 8 * nt + coff) = v0;
        *reinterpret_cast<float2*>(obase + (size_t)(row0 + 8) * DV + 8 * nt + coff) = v1;
    }
}

// ---------------------------------------------------------------------------
extern "C" void kernel_launch(void* const* d_in, const int* in_sizes, int n_in,
                              void* d_out, int out_size)
{
    (void)in_sizes; (void)n_in; (void)out_size;
    const float* review = (const float*)d_in[0];
    const float* user   = (const float*)d_in[1];
    const float* item   = (const float*)d_in[2];
    const int*   adj_ur = (const int*)d_in[3];
    const int*   adj_ri = (const int*)d_in[4];
    const int*   adj_ir = (const int*)d_in[5];
    const int*   adj_ru = (const int*)d_in[6];
    const float* Wu     = (const float*)d_in[7];
    const float* Wi     = (const float*)d_in[8];
    float* out = (float*)d_out;

    cudaFuncSetAttribute(build_v_kernel,
                         cudaFuncAttributeMaxDynamicSharedMemorySize, SMEM_BUILD);
    cudaFuncSetAttribute(flash_mma_kernel,
                         cudaFuncAttributeMaxDynamicSharedMemorySize, SMEM_FLASH);

    // blocks [0,128): V' GEMM; [128,144): Q split — fused, one launch
    build_v_kernel<<<dim3(NQ / 64 + 16, 2), 256, SMEM_BUILD>>>(
        review, user, item, adj_ur, adj_ri, adj_ir, adj_ru, Wu, Wi);

    dim3 grid(NQ / BM, 2);
    flash_mma_kernel<<<grid, 128, SMEM_FLASH>>>(out);
}